// round 14
// baseline (speedup 1.0000x reference)
#include <cuda_runtime.h>
#include <cuda_fp16.h>
#include <math.h>
#include <stdint.h>

#define BB 4
#define NTOK 4096
#define CC 256
#define BNTOK (BB * NTOK)   // 16384

// ---------------- static scratch ----------------
__device__ __half gQh [(size_t)BNTOK * CC];
__device__ __half gKh [(size_t)BNTOK * CC];
__device__ __half gVh [(size_t)BNTOK * CC];
__device__ float  gZ  [(size_t)BNTOK * CC];
__device__ float  gPE [(size_t)BNTOK * CC];
__device__ __half gTh [(size_t)BNTOK * CC];
__device__ __half gPh [(size_t)BB * NTOK * NTOK];    // 128 MB: E = exp(scaled logits)
__device__ float  gL  [BNTOK];                       // row sums of E
__device__ __half gXh [(size_t)BNTOK * CC];
__device__ __half gWqkvh[CC * 3 * CC];
__device__ __half gWgateh[CC * CC];
__device__ __half gWprojh[CC * CC];

__device__ __forceinline__ void cpa16(uint32_t dst, const void* src) {
    asm volatile("cp.async.ca.shared.global [%0], [%1], 16;" :: "r"(dst), "l"(src));
}
__device__ __forceinline__ void ldmx4(uint32_t r[4], uint32_t addr) {
    asm volatile("ldmatrix.sync.aligned.m8n8.x4.shared.b16 {%0,%1,%2,%3}, [%4];"
                 : "=r"(r[0]), "=r"(r[1]), "=r"(r[2]), "=r"(r[3]) : "r"(addr));
}
__device__ __forceinline__ void ldmx2(uint32_t r[2], uint32_t addr) {
    asm volatile("ldmatrix.sync.aligned.m8n8.x2.shared.b16 {%0,%1}, [%2];"
                 : "=r"(r[0]), "=r"(r[1]) : "r"(addr));
}
__device__ __forceinline__ void ldmx2t(uint32_t r[2], uint32_t addr) {
    asm volatile("ldmatrix.sync.aligned.m8n8.x2.trans.shared.b16 {%0,%1}, [%2];"
                 : "=r"(r[0]), "=r"(r[1]) : "r"(addr));
}
__device__ __forceinline__ void mma_f16(float d[4], const uint32_t a[4],
                                        uint32_t b0, uint32_t b1) {
    asm volatile(
        "mma.sync.aligned.m16n8k16.row.col.f32.f16.f16.f32 "
        "{%0,%1,%2,%3}, {%4,%5,%6,%7}, {%8,%9}, {%0,%1,%2,%3};"
        : "+f"(d[0]), "+f"(d[1]), "+f"(d[2]), "+f"(d[3])
        : "r"(a[0]), "r"(a[1]), "r"(a[2]), "r"(a[3]), "r"(b0), "r"(b1));
}
__device__ __forceinline__ void waitK(int n, int cap) {
    n = n < cap ? n : cap;
    switch (n) {
        case 0: asm volatile("cp.async.wait_group 0;"); break;
        case 1: asm volatile("cp.async.wait_group 1;"); break;
        default: asm volatile("cp.async.wait_group 2;"); break;
    }
}

#define ASTG 10240                 // A stage: 128 rows * 80 B
#define BSTG_D 10240               // B direct stage
#define BSTG_T 8704                // B trans stage: 32 rows * 272 B
#define NSTAGE 4

// ======================================================================
// fp16 GEMM: 256 thr, tile 128x128, BK=32, 4-stage.
// MODE 0: qkv split -> gQh/gKh/gVh
// MODE 1: gZ = gelu(acc+bias) (fp32)
// MODE 3: gTh = half((acc/L + gPE) * gZ)   (bz = blockIdx.z + bzOff)
// MODE 4: Out = acc (fp32)
// ======================================================================
template<int MODE, int TRB>
__global__ void __launch_bounds__(256, 2)
hgemm(const __half* __restrict__ A, const __half* __restrict__ B, float* __restrict__ Out,
      int K, int lda, int ldb, size_t sA, size_t sB, const float* __restrict__ bias,
      int bzOff)
{
    extern __shared__ __align__(16) char sm[];
    constexpr int BSTG = TRB ? BSTG_D : BSTG_T;
    const uint32_t smb = (uint32_t)__cvta_generic_to_shared(sm);
    const uint32_t aBase = smb;
    const uint32_t bBase = smb + NSTAGE * ASTG;

    const int tid  = threadIdx.x;
    const int wid  = tid >> 5;
    const int lane = tid & 31;
    const int g    = lane >> 2;
    const int t    = lane & 3;
    const int wm   = wid >> 2;
    const int wn   = wid & 3;

    const int bz     = blockIdx.z + bzOff;
    const int rowBlk = blockIdx.y * 128;
    const int colBlk = blockIdx.x * 128;
    const __half* Ab = A + (size_t)blockIdx.z * sA;
    const __half* Bb = B + (size_t)blockIdx.z * sB;
    const int NC = K >> 5;

    float d[4][4][4];
    #pragma unroll
    for (int mi = 0; mi < 4; mi++)
        #pragma unroll
        for (int ni = 0; ni < 4; ni++)
            #pragma unroll
            for (int j = 0; j < 4; j++) d[mi][ni][j] = 0.0f;

    auto loadStage = [&](int c) {
        const int kt = c << 5;
        const int sb = c & (NSTAGE - 1);
        const uint32_t aS = aBase + sb * ASTG;
        #pragma unroll
        for (int j = 0; j < 2; j++) {
            const int task = tid + j * 256;
            const int row = task >> 2, ch = task & 3;
            cpa16(aS + row * 80 + ch * 16,
                  Ab + (size_t)(rowBlk + row) * lda + kt + ch * 8);
        }
        const uint32_t bS = bBase + sb * BSTG;
        if (TRB) {
            #pragma unroll
            for (int j = 0; j < 2; j++) {
                const int task = tid + j * 256;
                const int row = task >> 2, ch = task & 3;
                cpa16(bS + row * 80 + ch * 16,
                      Bb + (size_t)(colBlk + row) * ldb + kt + ch * 8);
            }
        } else {
            #pragma unroll
            for (int j = 0; j < 2; j++) {
                const int task = tid + j * 256;
                const int row = task >> 4, ch = task & 15;
                cpa16(bS + row * 272 + ch * 16,
                      Bb + (size_t)(kt + row) * ldb + colBlk + ch * 8);
            }
        }
        asm volatile("cp.async.commit_group;");
    };

    loadStage(0); loadStage(1); loadStage(2);

    for (int c = 0; c < NC; ++c) {
        waitK(NC - 1 - c, NSTAGE - 2);
        __syncthreads();
        if (c + 3 < NC) loadStage(c + 3);

        const int sb = c & (NSTAGE - 1);
        const uint32_t aS = aBase + sb * ASTG;
        const uint32_t bS = bBase + sb * BSTG;

        #pragma unroll
        for (int s = 0; s < 2; s++) {
            const int k0 = 16 * s;
            uint32_t a[4][4];
            #pragma unroll
            for (int mi = 0; mi < 4; mi++)
                ldmx4(a[mi], aS + ((wm * 64 + mi * 16 + (lane & 15)) * 40
                                   + k0 + (lane >> 4) * 8) * 2);
            uint32_t b[4][2];
            #pragma unroll
            for (int ni = 0; ni < 4; ni++) {
                if (TRB)
                    ldmx2(b[ni], bS + ((wn * 32 + ni * 8 + (lane & 7)) * 40
                                       + k0 + ((lane >> 3) & 1) * 8) * 2);
                else
                    ldmx2t(b[ni], bS + ((k0 + (lane & 15)) * 136 + wn * 32 + ni * 8) * 2);
            }
            #pragma unroll
            for (int mi = 0; mi < 4; mi++)
                #pragma unroll
                for (int ni = 0; ni < 4; ni++)
                    mma_f16(d[mi][ni], a[mi], b[ni][0], b[ni][1]);
        }
        __syncthreads();
    }

    // ---- epilogue ----
    #pragma unroll
    for (int mi = 0; mi < 4; mi++) {
        #pragma unroll
        for (int hf = 0; hf < 2; hf++) {
            const int r = rowBlk + wm * 64 + mi * 16 + g + hf * 8;

            float invL = 1.0f;
            if (MODE == 3) invL = 1.0f / gL[bz * NTOK + r];

            #pragma unroll
            for (int ni = 0; ni < 4; ni++) {
                const int c = colBlk + wn * 32 + ni * 8 + 2 * t;
                float v0 = d[mi][ni][2 * hf + 0];
                float v1 = d[mi][ni][2 * hf + 1];

                if (MODE == 3) {
                    const size_t idx = ((size_t)(bz * NTOK + r)) * CC + c;
                    float2 pe = *(const float2*)&gPE[idx];
                    float2 zz = *(const float2*)&gZ[idx];
                    *(__half2*)&gTh[idx] =
                        __floats2half2_rn((v0 * invL + pe.x) * zz.x,
                                          (v1 * invL + pe.y) * zz.y);
                } else if (MODE == 0) {
                    const int seg = c >> 8;
                    const int cc = c & 255;
                    const size_t idx = (size_t)r * CC + cc;
                    __half2 hv = __floats2half2_rn(v0, v1);
                    __half* dst = (seg == 0) ? gQh : (seg == 1) ? gKh : gVh;
                    *(__half2*)&dst[idx] = hv;
                } else if (MODE == 1) {
                    float2 bb = *(const float2*)&bias[c];
                    float a0 = v0 + bb.x, a1 = v1 + bb.y;
                    float2 v;
                    v.x = 0.5f * a0 * (1.0f + erff(a0 * 0.70710678118654752f));
                    v.y = 0.5f * a1 * (1.0f + erff(a1 * 0.70710678118654752f));
                    *(float2*)&gZ[(size_t)r * CC + c] = v;
                } else {
                    *(float2*)&Out[(size_t)r * CC + c] = make_float2(v0, v1);
                }
            }
        }
    }
}

// ======================================================================
// QK GEMM: BK=64, 3-stage. Tile 128x128. Per-batch launch via bz arg.
// Epilogue: gPh = half(exp(acc*0.0625)); gL[row] += rowsum.
// ======================================================================
#define QSTG 18432        // 128 * 144
#define QK_NST 3
#define SMQK (QK_NST * 2 * QSTG)   // 110592

__global__ void __launch_bounds__(256, 2)
hgemm_qk(const __half* __restrict__ A, const __half* __restrict__ B, int bz)
{
    extern __shared__ __align__(16) char sm[];
    const uint32_t smb = (uint32_t)__cvta_generic_to_shared(sm);

    const int tid  = threadIdx.x;
    const int wid  = tid >> 5;
    const int lane = tid & 31;
    const int g    = lane >> 2;
    const int t    = lane & 3;
    const int wm   = wid >> 2;
    const int wn   = wid & 3;

    const int rowBlk = blockIdx.y * 128;
    const int colBlk = blockIdx.x * 128;
    const __half* Ab = A + (size_t)bz * NTOK * CC;
    const __half* Bb = B + (size_t)bz * NTOK * CC;
    const int NC = CC >> 6;    // 4

    float d[4][4][4];
    #pragma unroll
    for (int mi = 0; mi < 4; mi++)
        #pragma unroll
        for (int ni = 0; ni < 4; ni++)
            #pragma unroll
            for (int j = 0; j < 4; j++) d[mi][ni][j] = 0.0f;

    auto loadStage = [&](int c) {
        const int kt = c << 6;
        const int sb = c % QK_NST;
        const uint32_t aS = smb + sb * (2 * QSTG);
        const uint32_t bS = aS + QSTG;
        #pragma unroll
        for (int j = 0; j < 4; j++) {
            const int task = tid + j * 256;
            const int row = task >> 3, ch = task & 7;
            cpa16(aS + row * 144 + ch * 16,
                  Ab + (size_t)(rowBlk + row) * CC + kt + ch * 8);
        }
        #pragma unroll
        for (int j = 0; j < 4; j++) {
            const int task = tid + j * 256;
            const int row = task >> 3, ch = task & 7;
            cpa16(bS + row * 144 + ch * 16,
                  Bb + (size_t)(colBlk + row) * CC + kt + ch * 8);
        }
        asm volatile("cp.async.commit_group;");
    };

    loadStage(0); loadStage(1);

    for (int c = 0; c < NC; ++c) {
        waitK(NC - 1 - c, QK_NST - 2);
        __syncthreads();
        if (c + QK_NST - 1 < NC) loadStage(c + QK_NST - 1);

        const int sb = c % QK_NST;
        const uint32_t aS = smb + sb * (2 * QSTG);
        const uint32_t bS = aS + QSTG;

        #pragma unroll
        for (int s = 0; s < 4; s++) {
            const int k0 = 16 * s;
            uint32_t a[4][4];
            #pragma unroll
            for (int mi = 0; mi < 4; mi++)
                ldmx4(a[mi], aS + ((wm * 64 + mi * 16 + (lane & 15)) * 72
                                   + k0 + (lane >> 4) * 8) * 2);
            uint32_t b[4][2];
            #pragma unroll
            for (int ni = 0; ni < 4; ni++)
                ldmx2(b[ni], bS + ((wn * 32 + ni * 8 + (lane & 7)) * 72
                                   + k0 + ((lane >> 3) & 1) * 8) * 2);
            #pragma unroll
            for (int mi = 0; mi < 4; mi++)
                #pragma unroll
                for (int ni = 0; ni < 4; ni++)
                    mma_f16(d[mi][ni], a[mi], b[ni][0], b[ni][1]);
        }
        __syncthreads();
    }

    // ---- epilogue: E = exp(scale * acc), rowsum atomics ----
    #pragma unroll
    for (int mi = 0; mi < 4; mi++) {
        #pragma unroll
        for (int hf = 0; hf < 2; hf++) {
            const int r = rowBlk + wm * 64 + mi * 16 + g + hf * 8;
            float rsum = 0.0f;
            #pragma unroll
            for (int ni = 0; ni < 4; ni++) {
                const int c = colBlk + wn * 32 + ni * 8 + 2 * t;
                float e0 = __expf(d[mi][ni][2 * hf + 0] * 0.0625f);
                float e1 = __expf(d[mi][ni][2 * hf + 1] * 0.0625f);
                __half2 hv = __floats2half2_rn(e0, e1);
                *(__half2*)&gPh[(size_t)bz * NTOK * NTOK + (size_t)r * NTOK + c] = hv;
                rsum += __low2float(hv) + __high2float(hv);
            }
            rsum += __shfl_xor_sync(0xffffffffu, rsum, 1);
            rsum += __shfl_xor_sync(0xffffffffu, rsum, 2);
            if (t == 0) atomicAdd(&gL[bz * NTOK + r], rsum);
        }
    }
}

// ---------------- fused convert (x + 3 weights -> fp16) + zero gL ----------------
#define N2_X   (BNTOK * CC / 2)
#define N2_QKV (CC * 3 * CC / 2)
#define N2_GW  (CC * CC / 2)
__global__ void __launch_bounds__(256)
convert_all(const float* __restrict__ x, const float* __restrict__ Wqkv,
            const float* __restrict__ Wgate, const float* __restrict__ Wproj)
{
    int i = blockIdx.x * 256 + threadIdx.x;
    if (i < BNTOK) gL[i] = 0.0f;

    const float* src; __half* dst; int off;
    if (i < N2_X)                        { src = x;     dst = gXh;     off = i; }
    else if ((i -= N2_X) < N2_QKV)       { src = Wqkv;  dst = gWqkvh;  off = i; }
    else if ((i -= N2_QKV) < N2_GW)      { src = Wgate; dst = gWgateh; off = i; }
    else if ((i -= N2_GW) < N2_GW)       { src = Wproj; dst = gWprojh; off = i; }
    else return;
    float2 v = *(const float2*)(src + 2 * off);
    *(__half2*)(dst + 2 * off) = __floats2half2_rn(v.x, v.y);
}

// ---------------- depthwise 3x3 conv PE (half2 reads, fp32 out) ----------------
__global__ void __launch_bounds__(256)
dwconv_pe(const float* __restrict__ w, const float* __restrict__ bias)
{
    const int idx = blockIdx.x * 256 + threadIdx.x;   // over BNTOK * 128
    const int c2 = idx & 127;
    const int n = (idx >> 7) & (NTOK - 1);
    const int b = idx >> 19;
    const int h = n >> 6;
    const int wd = n & 63;
    const int c = 2 * c2;

    const __half* q = gQh + (size_t)b * NTOK * CC;
    float a0 = bias[c], a1 = bias[c + 1];
    #pragma unroll
    for (int di = -1; di <= 1; di++) {
        const int hh = h + di;
        if (hh < 0 || hh > 63) continue;
        #pragma unroll
        for (int dj = -1; dj <= 1; dj++) {
            const int w2 = wd + dj;
            if (w2 < 0 || w2 > 63) continue;
            float2 qv = __half22float2(*(const __half2*)&q[(size_t)(hh * 64 + w2) * CC + c]);
            const int wj = (di + 1) * 3 + (dj + 1);
            a0 = fmaf(qv.x, w[c * 9 + wj], a0);
            a1 = fmaf(qv.y, w[(c + 1) * 9 + wj], a1);
        }
    }
    *(float2*)&gPE[2 * (size_t)idx] = make_float2(a0, a1);
}

// ---------------- launch ----------------
extern "C" void kernel_launch(void* const* d_in, const int* in_sizes, int n_in,
                              void* d_out, int out_size)
{
    const float* x     = (const float*)d_in[0];
    const float* Wqkv  = (const float*)d_in[1];
    const float* Wgate = (const float*)d_in[2];
    const float* bgate = (const float*)d_in[3];
    const float* Wproj = (const float*)d_in[4];
    const float* pew   = (const float*)d_in[5];
    const float* peb   = (const float*)d_in[6];
    float* out = (float*)d_out;

    __half *pXh, *pWqkvh, *pWgateh, *pWprojh, *pQh, *pKh, *pVh, *pPh, *pTh;
    cudaGetSymbolAddress((void**)&pXh, gXh);
    cudaGetSymbolAddress((void**)&pWqkvh, gWqkvh);
    cudaGetSymbolAddress((void**)&pWgateh, gWgateh);
    cudaGetSymbolAddress((void**)&pWprojh, gWprojh);
    cudaGetSymbolAddress((void**)&pQh, gQh);
    cudaGetSymbolAddress((void**)&pKh, gKh);
    cudaGetSymbolAddress((void**)&pVh, gVh);
    cudaGetSymbolAddress((void**)&pPh, gPh);
    cudaGetSymbolAddress((void**)&pTh, gTh);

    // one-time streams + events
    static cudaStream_t s2 = nullptr, s3 = nullptr;
    static cudaEvent_t evFork = nullptr, evJoin = nullptr, evPV = nullptr;
    static cudaEvent_t evQK[BB] = {nullptr, nullptr, nullptr, nullptr};
    if (s2 == nullptr) {
        cudaStreamCreateWithFlags(&s2, cudaStreamNonBlocking);
        cudaStreamCreateWithFlags(&s3, cudaStreamNonBlocking);
        cudaEventCreateWithFlags(&evFork, cudaEventDisableTiming);
        cudaEventCreateWithFlags(&evJoin, cudaEventDisableTiming);
        cudaEventCreateWithFlags(&evPV, cudaEventDisableTiming);
        for (int b = 0; b < BB; b++)
            cudaEventCreateWithFlags(&evQK[b], cudaEventDisableTiming);
    }

    constexpr int SMT = NSTAGE * (ASTG + BSTG_T);   // 75776
    cudaFuncSetAttribute(hgemm<0,0>, cudaFuncAttributeMaxDynamicSharedMemorySize, SMT);
    cudaFuncSetAttribute(hgemm<1,0>, cudaFuncAttributeMaxDynamicSharedMemorySize, SMT);
    cudaFuncSetAttribute(hgemm<3,0>, cudaFuncAttributeMaxDynamicSharedMemorySize, SMT);
    cudaFuncSetAttribute(hgemm<4,0>, cudaFuncAttributeMaxDynamicSharedMemorySize, SMT);
    cudaFuncSetAttribute(hgemm_qk, cudaFuncAttributeMaxDynamicSharedMemorySize, SMQK);

    // 0) converts + zero row sums
    const int cvt_n = N2_X + N2_QKV + 2 * N2_GW;
    convert_all<<<dim3((cvt_n + 255) / 256), 256>>>(x, Wqkv, Wgate, Wproj);

    // 1) qkv = x @ W_qkv -> gQh/gKh/gVh
    hgemm<0,0><<<dim3(6,128,1), 256, SMT>>>(pXh, pWqkvh, nullptr, 256, 256, 768,
                                            0, 0, nullptr, 0);

    // fork: gate + dwconv on s2 (PV needs both)
    cudaEventRecord(evFork, 0);
    cudaStreamWaitEvent(s2, evFork, 0);
    hgemm<1,0><<<dim3(2,128,1), 256, SMT, s2>>>(pXh, pWgateh, nullptr, 256, 256, 256,
                                                0, 0, bgate, 0);
    dwconv_pe<<<dim3(BNTOK * 128 / 256), 256, 0, s2>>>(pew, peb);
    cudaEventRecord(evJoin, s2);
    cudaStreamWaitEvent(s3, evJoin, 0);

    // 2) batch-pipelined QK (main) -> PV (s3)
    for (int bz = 0; bz < BB; bz++) {
        hgemm_qk<<<dim3(32,32,1), 256, SMQK>>>(pQh, pKh, bz);
        cudaEventRecord(evQK[bz], 0);
        cudaStreamWaitEvent(s3, evQK[bz], 0);
        hgemm<3,0><<<dim3(2,32,1), 256, SMT, s3>>>(
            pPh + (size_t)bz * NTOK * NTOK, pVh + (size_t)bz * NTOK * CC, nullptr,
            4096, 4096, 256, 0, 0, nullptr, bz);
    }
    cudaEventRecord(evPV, s3);
    cudaStreamWaitEvent(0, evPV, 0);

    // 3) out = T @ W_proj
    hgemm<4,0><<<dim3(2,128,1), 256, SMT>>>(pTh, pWprojh, out, 256, 256, 256,
                                            0, 0, nullptr, 0);
}

// round 15
// speedup vs baseline: 1.5320x; 1.5320x over previous
#include <cuda_runtime.h>
#include <cuda_fp16.h>
#include <math.h>
#include <stdint.h>

#define BB 4
#define NTOK 4096
#define CC 256
#define BNTOK (BB * NTOK)   // 16384

// ---------------- static scratch ----------------
__device__ __half gQh [(size_t)BNTOK * CC];
__device__ __half gKh [(size_t)BNTOK * CC];
__device__ __half gVh [(size_t)BNTOK * CC];
__device__ float  gZ  [(size_t)BNTOK * CC];
__device__ float  gPE [(size_t)BNTOK * CC];
__device__ __half gTh [(size_t)BNTOK * CC];
__device__ __half gPh [(size_t)BB * NTOK * NTOK];    // 128 MB: E = exp(scaled logits)
__device__ float  gL  [BNTOK];                       // row sums of E
__device__ __half gXh [(size_t)BNTOK * CC];
__device__ __half gWqkvh[CC * 3 * CC];
__device__ __half gWgateh[CC * CC];
__device__ __half gWprojh[CC * CC];

__device__ __forceinline__ void cpa16(uint32_t dst, const void* src) {
    asm volatile("cp.async.ca.shared.global [%0], [%1], 16;" :: "r"(dst), "l"(src));
}
__device__ __forceinline__ void cpa16cg(uint32_t dst, const void* src) {
    asm volatile("cp.async.cg.shared.global [%0], [%1], 16;" :: "r"(dst), "l"(src));
}
__device__ __forceinline__ void ldmx4(uint32_t r[4], uint32_t addr) {
    asm volatile("ldmatrix.sync.aligned.m8n8.x4.shared.b16 {%0,%1,%2,%3}, [%4];"
                 : "=r"(r[0]), "=r"(r[1]), "=r"(r[2]), "=r"(r[3]) : "r"(addr));
}
__device__ __forceinline__ void ldmx4t(uint32_t r[4], uint32_t addr) {
    asm volatile("ldmatrix.sync.aligned.m8n8.x4.trans.shared.b16 {%0,%1,%2,%3}, [%4];"
                 : "=r"(r[0]), "=r"(r[1]), "=r"(r[2]), "=r"(r[3]) : "r"(addr));
}
__device__ __forceinline__ void mma_f16(float d[4], const uint32_t a[4],
                                        uint32_t b0, uint32_t b1) {
    asm volatile(
        "mma.sync.aligned.m16n8k16.row.col.f32.f16.f16.f32 "
        "{%0,%1,%2,%3}, {%4,%5,%6,%7}, {%8,%9}, {%0,%1,%2,%3};"
        : "+f"(d[0]), "+f"(d[1]), "+f"(d[2]), "+f"(d[3])
        : "r"(a[0]), "r"(a[1]), "r"(a[2]), "r"(a[3]), "r"(b0), "r"(b1));
}
__device__ __forceinline__ void waitK(int n, int cap) {
    n = n < cap ? n : cap;
    switch (n) {
        case 0: asm volatile("cp.async.wait_group 0;"); break;
        case 1: asm volatile("cp.async.wait_group 1;"); break;
        default: asm volatile("cp.async.wait_group 2;"); break;
    }
}

#define ASTG 10240                 // A stage: 128 rows * 80 B
#define BSTG_D 10240               // B direct stage
#define BSTG_T 8704                // B trans stage: 32 rows * 272 B
#define NSTAGE 4

// ======================================================================
// fp16 GEMM: 256 thr, tile 128x128, BK=32, 4-stage.
// MODE 0: qkv split -> gQh/gKh/gVh
// MODE 1: gZ = gelu(acc+bias) (fp32)
// MODE 3: gTh = half((acc/L + gPE) * gZ)
// MODE 4: Out = acc (fp32)
// ======================================================================
template<int MODE, int TRB>
__global__ void __launch_bounds__(256, 2)
hgemm(const __half* __restrict__ A, const __half* __restrict__ B, float* __restrict__ Out,
      int K, int lda, int ldb, size_t sA, size_t sB, const float* __restrict__ bias)
{
    extern __shared__ __align__(16) char sm[];
    constexpr int BSTG = TRB ? BSTG_D : BSTG_T;
    const uint32_t smb = (uint32_t)__cvta_generic_to_shared(sm);
    const uint32_t aBase = smb;
    const uint32_t bBase = smb + NSTAGE * ASTG;

    const int tid  = threadIdx.x;
    const int wid  = tid >> 5;
    const int lane = tid & 31;
    const int g    = lane >> 2;
    const int t    = lane & 3;
    const int wm   = wid >> 2;
    const int wn   = wid & 3;

    const int bz     = blockIdx.z;
    const int rowBlk = blockIdx.y * 128;
    const int colBlk = blockIdx.x * 128;
    const __half* Ab = A + (size_t)bz * sA;
    const __half* Bb = B + (size_t)bz * sB;
    const int NC = K >> 5;

    float d[4][4][4];
    #pragma unroll
    for (int mi = 0; mi < 4; mi++)
        #pragma unroll
        for (int ni = 0; ni < 4; ni++)
            #pragma unroll
            for (int j = 0; j < 4; j++) d[mi][ni][j] = 0.0f;

    auto loadStage = [&](int c) {
        const int kt = c << 5;
        const int sb = c & (NSTAGE - 1);
        const uint32_t aS = aBase + sb * ASTG;
        #pragma unroll
        for (int j = 0; j < 2; j++) {
            const int task = tid + j * 256;
            const int row = task >> 2, ch = task & 3;
            if (MODE == 3)
                cpa16cg(aS + row * 80 + ch * 16,
                        Ab + (size_t)(rowBlk + row) * lda + kt + ch * 8);
            else
                cpa16(aS + row * 80 + ch * 16,
                      Ab + (size_t)(rowBlk + row) * lda + kt + ch * 8);
        }
        const uint32_t bS = bBase + sb * BSTG;
        if (TRB) {
            #pragma unroll
            for (int j = 0; j < 2; j++) {
                const int task = tid + j * 256;
                const int row = task >> 2, ch = task & 3;
                cpa16(bS + row * 80 + ch * 16,
                      Bb + (size_t)(colBlk + row) * ldb + kt + ch * 8);
            }
        } else {
            #pragma unroll
            for (int j = 0; j < 2; j++) {
                const int task = tid + j * 256;
                const int row = task >> 4, ch = task & 15;
                cpa16(bS + row * 272 + ch * 16,
                      Bb + (size_t)(kt + row) * ldb + colBlk + ch * 8);
            }
        }
        asm volatile("cp.async.commit_group;");
    };

    loadStage(0); loadStage(1); loadStage(2);

    for (int c = 0; c < NC; ++c) {
        waitK(NC - 1 - c, NSTAGE - 2);
        __syncthreads();
        if (c + 3 < NC) loadStage(c + 3);

        const int sb = c & (NSTAGE - 1);
        const uint32_t aS = aBase + sb * ASTG;
        const uint32_t bS = bBase + sb * BSTG;

        #pragma unroll
        for (int s = 0; s < 2; s++) {
            const int k0 = 16 * s;
            uint32_t a[4][4];
            #pragma unroll
            for (int mi = 0; mi < 4; mi++)
                ldmx4(a[mi], aS + ((wm * 64 + mi * 16 + (lane & 15)) * 40
                                   + k0 + (lane >> 4) * 8) * 2);
            uint32_t b[4][2];
            #pragma unroll
            for (int pr = 0; pr < 2; pr++) {
                uint32_t r[4];
                if (TRB) {
                    // rows n..n+15 (non-trans): r = {n0k0, n8k0, n0k8, n8k8}
                    ldmx4(r, bS + ((wn * 32 + pr * 16 + (lane & 15)) * 40
                                   + k0 + (lane >> 4) * 8) * 2);
                    b[2*pr+0][0] = r[0]; b[2*pr+0][1] = r[2];
                    b[2*pr+1][0] = r[1]; b[2*pr+1][1] = r[3];
                } else {
                    // trans: rows k0..k0+15, col n + (lane>>4)*8
                    // r = {n0 klo, n0 khi, n8 klo, n8 khi}
                    ldmx4t(r, bS + ((k0 + (lane & 15)) * 136
                                    + wn * 32 + pr * 16 + (lane >> 4) * 8) * 2);
                    b[2*pr+0][0] = r[0]; b[2*pr+0][1] = r[1];
                    b[2*pr+1][0] = r[2]; b[2*pr+1][1] = r[3];
                }
            }
            #pragma unroll
            for (int mi = 0; mi < 4; mi++)
                #pragma unroll
                for (int ni = 0; ni < 4; ni++)
                    mma_f16(d[mi][ni], a[mi], b[ni][0], b[ni][1]);
        }
        __syncthreads();
    }

    // ---- epilogue ----
    #pragma unroll
    for (int mi = 0; mi < 4; mi++) {
        #pragma unroll
        for (int hf = 0; hf < 2; hf++) {
            const int r = rowBlk + wm * 64 + mi * 16 + g + hf * 8;

            float invL = 1.0f;
            if (MODE == 3) invL = 1.0f / gL[bz * NTOK + r];

            #pragma unroll
            for (int ni = 0; ni < 4; ni++) {
                const int c = colBlk + wn * 32 + ni * 8 + 2 * t;
                float v0 = d[mi][ni][2 * hf + 0];
                float v1 = d[mi][ni][2 * hf + 1];

                if (MODE == 3) {
                    const size_t idx = ((size_t)(bz * NTOK + r)) * CC + c;
                    float2 pe = *(const float2*)&gPE[idx];
                    float2 zz = *(const float2*)&gZ[idx];
                    *(__half2*)&gTh[idx] =
                        __floats2half2_rn((v0 * invL + pe.x) * zz.x,
                                          (v1 * invL + pe.y) * zz.y);
                } else if (MODE == 0) {
                    const int seg = c >> 8;
                    const int cc = c & 255;
                    const size_t idx = (size_t)r * CC + cc;
                    __half2 hv = __floats2half2_rn(v0, v1);
                    __half* dst = (seg == 0) ? gQh : (seg == 1) ? gKh : gVh;
                    *(__half2*)&dst[idx] = hv;
                } else if (MODE == 1) {
                    float2 bb = *(const float2*)&bias[c];
                    float a0 = v0 + bb.x, a1 = v1 + bb.y;
                    float2 v;
                    v.x = 0.5f * a0 * (1.0f + erff(a0 * 0.70710678118654752f));
                    v.y = 0.5f * a1 * (1.0f + erff(a1 * 0.70710678118654752f));
                    *(float2*)&gZ[(size_t)r * CC + c] = v;
                } else {
                    *(float2*)&Out[(size_t)r * CC + c] = make_float2(v0, v1);
                }
            }
        }
    }
}

// ======================================================================
// QK GEMM: BK=64, 3-stage. Tile 128x128. Both A,B [N,K] K-contig.
// Epilogue: gPh = half(exp(acc*0.0625)); gL[row] += rowsum.
// ======================================================================
#define QSTG 18432        // 128 * 144
#define QK_NST 3
#define SMQK (QK_NST * 2 * QSTG)   // 110592

__global__ void __launch_bounds__(256, 2)
hgemm_qk(const __half* __restrict__ A, const __half* __restrict__ B)
{
    extern __shared__ __align__(16) char sm[];
    const uint32_t smb = (uint32_t)__cvta_generic_to_shared(sm);

    const int tid  = threadIdx.x;
    const int wid  = tid >> 5;
    const int lane = tid & 31;
    const int g    = lane >> 2;
    const int t    = lane & 3;
    const int wm   = wid >> 2;
    const int wn   = wid & 3;

    const int bz     = blockIdx.z;
    const int rowBlk = blockIdx.y * 128;
    const int colBlk = blockIdx.x * 128;
    const __half* Ab = A + (size_t)bz * NTOK * CC;
    const __half* Bb = B + (size_t)bz * NTOK * CC;
    const int NC = CC >> 6;    // 4

    float d[4][4][4];
    #pragma unroll
    for (int mi = 0; mi < 4; mi++)
        #pragma unroll
        for (int ni = 0; ni < 4; ni++)
            #pragma unroll
            for (int j = 0; j < 4; j++) d[mi][ni][j] = 0.0f;

    auto loadStage = [&](int c) {
        const int kt = c << 6;
        const int sb = c % QK_NST;
        const uint32_t aS = smb + sb * (2 * QSTG);
        const uint32_t bS = aS + QSTG;
        #pragma unroll
        for (int j = 0; j < 4; j++) {
            const int task = tid + j * 256;
            const int row = task >> 3, ch = task & 7;
            cpa16(aS + row * 144 + ch * 16,
                  Ab + (size_t)(rowBlk + row) * CC + kt + ch * 8);
        }
        #pragma unroll
        for (int j = 0; j < 4; j++) {
            const int task = tid + j * 256;
            const int row = task >> 3, ch = task & 7;
            cpa16(bS + row * 144 + ch * 16,
                  Bb + (size_t)(colBlk + row) * CC + kt + ch * 8);
        }
        asm volatile("cp.async.commit_group;");
    };

    loadStage(0); loadStage(1);

    for (int c = 0; c < NC; ++c) {
        waitK(NC - 1 - c, QK_NST - 2);
        __syncthreads();
        if (c + QK_NST - 1 < NC) loadStage(c + QK_NST - 1);

        const int sb = c % QK_NST;
        const uint32_t aS = smb + sb * (2 * QSTG);
        const uint32_t bS = aS + QSTG;

        #pragma unroll
        for (int s = 0; s < 4; s++) {
            const int k0 = 16 * s;
            uint32_t a[4][4];
            #pragma unroll
            for (int mi = 0; mi < 4; mi++)
                ldmx4(a[mi], aS + ((wm * 64 + mi * 16 + (lane & 15)) * 72
                                   + k0 + (lane >> 4) * 8) * 2);
            uint32_t b[4][2];
            #pragma unroll
            for (int pr = 0; pr < 2; pr++) {
                uint32_t r[4];
                ldmx4(r, bS + ((wn * 32 + pr * 16 + (lane & 15)) * 72
                               + k0 + (lane >> 4) * 8) * 2);
                b[2*pr+0][0] = r[0]; b[2*pr+0][1] = r[2];
                b[2*pr+1][0] = r[1]; b[2*pr+1][1] = r[3];
            }
            #pragma unroll
            for (int mi = 0; mi < 4; mi++)
                #pragma unroll
                for (int ni = 0; ni < 4; ni++)
                    mma_f16(d[mi][ni], a[mi], b[ni][0], b[ni][1]);
        }
        __syncthreads();
    }

    // ---- epilogue: E = exp(scale * acc), rowsum atomics ----
    #pragma unroll
    for (int mi = 0; mi < 4; mi++) {
        #pragma unroll
        for (int hf = 0; hf < 2; hf++) {
            const int r = rowBlk + wm * 64 + mi * 16 + g + hf * 8;
            float rsum = 0.0f;
            #pragma unroll
            for (int ni = 0; ni < 4; ni++) {
                const int c = colBlk + wn * 32 + ni * 8 + 2 * t;
                float e0 = __expf(d[mi][ni][2 * hf + 0] * 0.0625f);
                float e1 = __expf(d[mi][ni][2 * hf + 1] * 0.0625f);
                __half2 hv = __floats2half2_rn(e0, e1);
                *(__half2*)&gPh[(size_t)bz * NTOK * NTOK + (size_t)r * NTOK + c] = hv;
                rsum += __low2float(hv) + __high2float(hv);
            }
            rsum += __shfl_xor_sync(0xffffffffu, rsum, 1);
            rsum += __shfl_xor_sync(0xffffffffu, rsum, 2);
            if (t == 0) atomicAdd(&gL[bz * NTOK + r], rsum);
        }
    }
}

// ---------------- fused convert (x + 3 weights -> fp16) + zero gL ----------------
#define N2_X   (BNTOK * CC / 2)
#define N2_QKV (CC * 3 * CC / 2)
#define N2_GW  (CC * CC / 2)
__global__ void __launch_bounds__(256)
convert_all(const float* __restrict__ x, const float* __restrict__ Wqkv,
            const float* __restrict__ Wgate, const float* __restrict__ Wproj)
{
    int i = blockIdx.x * 256 + threadIdx.x;
    if (i < BNTOK) gL[i] = 0.0f;

    const float* src; __half* dst; int off;
    if (i < N2_X)                        { src = x;     dst = gXh;     off = i; }
    else if ((i -= N2_X) < N2_QKV)       { src = Wqkv;  dst = gWqkvh;  off = i; }
    else if ((i -= N2_QKV) < N2_GW)      { src = Wgate; dst = gWgateh; off = i; }
    else if ((i -= N2_GW) < N2_GW)       { src = Wproj; dst = gWprojh; off = i; }
    else return;
    float2 v = *(const float2*)(src + 2 * off);
    *(__half2*)(dst + 2 * off) = __floats2half2_rn(v.x, v.y);
}

// ---------------- depthwise 3x3 conv PE (half2 reads, fp32 out) ----------------
__global__ void __launch_bounds__(256)
dwconv_pe(const float* __restrict__ w, const float* __restrict__ bias)
{
    const int idx = blockIdx.x * 256 + threadIdx.x;   // over BNTOK * 128
    const int c2 = idx & 127;
    const int n = (idx >> 7) & (NTOK - 1);
    const int b = idx >> 19;
    const int h = n >> 6;
    const int wd = n & 63;
    const int c = 2 * c2;

    const __half* q = gQh + (size_t)b * NTOK * CC;
    float a0 = bias[c], a1 = bias[c + 1];
    #pragma unroll
    for (int di = -1; di <= 1; di++) {
        const int hh = h + di;
        if (hh < 0 || hh > 63) continue;
        #pragma unroll
        for (int dj = -1; dj <= 1; dj++) {
            const int w2 = wd + dj;
            if (w2 < 0 || w2 > 63) continue;
            float2 qv = __half22float2(*(const __half2*)&q[(size_t)(hh * 64 + w2) * CC + c]);
            const int wj = (di + 1) * 3 + (dj + 1);
            a0 = fmaf(qv.x, w[c * 9 + wj], a0);
            a1 = fmaf(qv.y, w[(c + 1) * 9 + wj], a1);
        }
    }
    *(float2*)&gPE[2 * (size_t)idx] = make_float2(a0, a1);
}

// ---------------- launch ----------------
extern "C" void kernel_launch(void* const* d_in, const int* in_sizes, int n_in,
                              void* d_out, int out_size)
{
    const float* x     = (const float*)d_in[0];
    const float* Wqkv  = (const float*)d_in[1];
    const float* Wgate = (const float*)d_in[2];
    const float* bgate = (const float*)d_in[3];
    const float* Wproj = (const float*)d_in[4];
    const float* pew   = (const float*)d_in[5];
    const float* peb   = (const float*)d_in[6];
    float* out = (float*)d_out;

    __half *pXh, *pWqkvh, *pWgateh, *pWprojh, *pQh, *pKh, *pVh, *pPh, *pTh;
    cudaGetSymbolAddress((void**)&pXh, gXh);
    cudaGetSymbolAddress((void**)&pWqkvh, gWqkvh);
    cudaGetSymbolAddress((void**)&pWgateh, gWgateh);
    cudaGetSymbolAddress((void**)&pWprojh, gWprojh);
    cudaGetSymbolAddress((void**)&pQh, gQh);
    cudaGetSymbolAddress((void**)&pKh, gKh);
    cudaGetSymbolAddress((void**)&pVh, gVh);
    cudaGetSymbolAddress((void**)&pPh, gPh);
    cudaGetSymbolAddress((void**)&pTh, gTh);

    // one-time side-stream + events
    static cudaStream_t s2 = nullptr;
    static cudaEvent_t evFork = nullptr, evJoin = nullptr;
    if (s2 == nullptr) {
        cudaStreamCreateWithFlags(&s2, cudaStreamNonBlocking);
        cudaEventCreateWithFlags(&evFork, cudaEventDisableTiming);
        cudaEventCreateWithFlags(&evJoin, cudaEventDisableTiming);
    }

    constexpr int SMT = NSTAGE * (ASTG + BSTG_T);   // 75776
    cudaFuncSetAttribute(hgemm<0,0>, cudaFuncAttributeMaxDynamicSharedMemorySize, SMT);
    cudaFuncSetAttribute(hgemm<1,0>, cudaFuncAttributeMaxDynamicSharedMemorySize, SMT);
    cudaFuncSetAttribute(hgemm<3,0>, cudaFuncAttributeMaxDynamicSharedMemorySize, SMT);
    cudaFuncSetAttribute(hgemm<4,0>, cudaFuncAttributeMaxDynamicSharedMemorySize, SMT);
    cudaFuncSetAttribute(hgemm_qk, cudaFuncAttributeMaxDynamicSharedMemorySize, SMQK);

    // 0) converts + zero row sums
    const int cvt_n = N2_X + N2_QKV + 2 * N2_GW;
    convert_all<<<dim3((cvt_n + 255) / 256), 256>>>(x, Wqkv, Wgate, Wproj);

    // 1) qkv = x @ W_qkv -> gQh/gKh/gVh
    hgemm<0,0><<<dim3(6,128,1), 256, SMT>>>(pXh, pWqkvh, nullptr, 256, 256, 768, 0, 0, nullptr);

    // fork: gate + dwconv on side stream, QK on main
    cudaEventRecord(evFork, 0);
    cudaStreamWaitEvent(s2, evFork, 0);
    hgemm<1,0><<<dim3(2,128,1), 256, SMT, s2>>>(pXh, pWgateh, nullptr, 256, 256, 256,
                                                0, 0, bgate);
    dwconv_pe<<<dim3(BNTOK * 128 / 256), 256, 0, s2>>>(pew, peb);
    cudaEventRecord(evJoin, s2);

    // main: E = exp(scale * Q K^T), row sums into gL (BK=64, 3-stage)
    hgemm_qk<<<dim3(32,32,BB), 256, SMQK>>>(pQh, pKh);

    // join before PV
    cudaStreamWaitEvent(0, evJoin, 0);

    // 5) T = (E @ V / L + PE) * Z -> gTh  (BK=32, 4-stage, E loads via .cg)
    hgemm<3,0><<<dim3(2,32,BB), 256, SMT>>>(pPh, pVh, nullptr, 4096, 4096, 256,
                                            (size_t)NTOK * NTOK, (size_t)NTOK * CC, nullptr);
    // 6) out = T @ W_proj
    hgemm<4,0><<<dim3(2,128,1), 256, SMT>>>(pTh, pWprojh, out, 256, 256, 256, 0, 0, nullptr);
}

// round 16
// speedup vs baseline: 1.5729x; 1.0267x over previous
#include <cuda_runtime.h>
#include <cuda_fp16.h>
#include <math.h>
#include <stdint.h>

#define BB 4
#define NTOK 4096
#define CC 256
#define BNTOK (BB * NTOK)   // 16384

// ---------------- static scratch ----------------
__device__ __half gQh [(size_t)BNTOK * CC];
__device__ __half gKh [(size_t)BNTOK * CC];
__device__ __half gVh [(size_t)BNTOK * CC];
__device__ float  gZ  [(size_t)BNTOK * CC];
__device__ float  gPE [(size_t)BNTOK * CC];
__device__ __half gTh [(size_t)BNTOK * CC];
__device__ __half gPh [(size_t)BB * NTOK * NTOK];    // 128 MB: E = exp(scaled logits)
__device__ float  gL  [BNTOK];                       // row sums of E
__device__ __half gXh [(size_t)BNTOK * CC];
__device__ __half gWqkvh[CC * 3 * CC];
__device__ __half gWgateh[CC * CC];
__device__ __half gWprojh[CC * CC];

__device__ __forceinline__ void cpa16(uint32_t dst, const void* src) {
    asm volatile("cp.async.ca.shared.global [%0], [%1], 16;" :: "r"(dst), "l"(src));
}
__device__ __forceinline__ void cpa16cg(uint32_t dst, const void* src) {
    asm volatile("cp.async.cg.shared.global [%0], [%1], 16;" :: "r"(dst), "l"(src));
}
__device__ __forceinline__ void ldmx4(uint32_t r[4], uint32_t addr) {
    asm volatile("ldmatrix.sync.aligned.m8n8.x4.shared.b16 {%0,%1,%2,%3}, [%4];"
                 : "=r"(r[0]), "=r"(r[1]), "=r"(r[2]), "=r"(r[3]) : "r"(addr));
}
__device__ __forceinline__ void ldmx4t(uint32_t r[4], uint32_t addr) {
    asm volatile("ldmatrix.sync.aligned.m8n8.x4.trans.shared.b16 {%0,%1,%2,%3}, [%4];"
                 : "=r"(r[0]), "=r"(r[1]), "=r"(r[2]), "=r"(r[3]) : "r"(addr));
}
__device__ __forceinline__ void mma_f16(float d[4], const uint32_t a[4],
                                        uint32_t b0, uint32_t b1) {
    asm volatile(
        "mma.sync.aligned.m16n8k16.row.col.f32.f16.f16.f32 "
        "{%0,%1,%2,%3}, {%4,%5,%6,%7}, {%8,%9}, {%0,%1,%2,%3};"
        : "+f"(d[0]), "+f"(d[1]), "+f"(d[2]), "+f"(d[3])
        : "r"(a[0]), "r"(a[1]), "r"(a[2]), "r"(a[3]), "r"(b0), "r"(b1));
}
__device__ __forceinline__ void waitK(int n, int cap) {
    n = n < cap ? n : cap;
    switch (n) {
        case 0: asm volatile("cp.async.wait_group 0;"); break;
        case 1: asm volatile("cp.async.wait_group 1;"); break;
        default: asm volatile("cp.async.wait_group 2;"); break;
    }
}

#define ASTG 10240                 // A stage: 128 rows * 80 B
#define BSTG_D 10240               // B direct stage
#define BSTG_T 8704                // B trans stage: 32 rows * 272 B
#define NSTAGE 4

// ======================================================================
// fp16 GEMM: 256 thr, tile 128x128, BK=32, 4-stage.
// MODE 0: qkv split -> gQh/gKh/gVh
// MODE 1: gZ = gelu(acc+bias) (fp32)
// MODE 3: gTh = half((acc/L + gPE) * gZ)   bz = blockIdx.z + bzOff
// MODE 4: Out = acc (fp32)
// ======================================================================
template<int MODE, int TRB>
__global__ void __launch_bounds__(256, 2)
hgemm(const __half* __restrict__ A, const __half* __restrict__ B, float* __restrict__ Out,
      int K, int lda, int ldb, size_t sA, size_t sB, const float* __restrict__ bias,
      int bzOff)
{
    extern __shared__ __align__(16) char sm[];
    constexpr int BSTG = TRB ? BSTG_D : BSTG_T;
    const uint32_t smb = (uint32_t)__cvta_generic_to_shared(sm);
    const uint32_t aBase = smb;
    const uint32_t bBase = smb + NSTAGE * ASTG;

    const int tid  = threadIdx.x;
    const int wid  = tid >> 5;
    const int lane = tid & 31;
    const int g    = lane >> 2;
    const int t    = lane & 3;
    const int wm   = wid >> 2;
    const int wn   = wid & 3;

    const int bz     = blockIdx.z + bzOff;
    const int rowBlk = blockIdx.y * 128;
    const int colBlk = blockIdx.x * 128;
    const __half* Ab = A + (size_t)blockIdx.z * sA;
    const __half* Bb = B + (size_t)blockIdx.z * sB;
    const int NC = K >> 5;

    float d[4][4][4];
    #pragma unroll
    for (int mi = 0; mi < 4; mi++)
        #pragma unroll
        for (int ni = 0; ni < 4; ni++)
            #pragma unroll
            for (int j = 0; j < 4; j++) d[mi][ni][j] = 0.0f;

    auto loadStage = [&](int c) {
        const int kt = c << 5;
        const int sb = c & (NSTAGE - 1);
        const uint32_t aS = aBase + sb * ASTG;
        #pragma unroll
        for (int j = 0; j < 2; j++) {
            const int task = tid + j * 256;
            const int row = task >> 2, ch = task & 3;
            if (MODE == 3)
                cpa16cg(aS + row * 80 + ch * 16,
                        Ab + (size_t)(rowBlk + row) * lda + kt + ch * 8);
            else
                cpa16(aS + row * 80 + ch * 16,
                      Ab + (size_t)(rowBlk + row) * lda + kt + ch * 8);
        }
        const uint32_t bS = bBase + sb * BSTG;
        if (TRB) {
            #pragma unroll
            for (int j = 0; j < 2; j++) {
                const int task = tid + j * 256;
                const int row = task >> 2, ch = task & 3;
                cpa16(bS + row * 80 + ch * 16,
                      Bb + (size_t)(colBlk + row) * ldb + kt + ch * 8);
            }
        } else {
            #pragma unroll
            for (int j = 0; j < 2; j++) {
                const int task = tid + j * 256;
                const int row = task >> 4, ch = task & 15;
                cpa16(bS + row * 272 + ch * 16,
                      Bb + (size_t)(kt + row) * ldb + colBlk + ch * 8);
            }
        }
        asm volatile("cp.async.commit_group;");
    };

    loadStage(0); loadStage(1); loadStage(2);

    for (int c = 0; c < NC; ++c) {
        waitK(NC - 1 - c, NSTAGE - 2);
        __syncthreads();
        if (c + 3 < NC) loadStage(c + 3);

        const int sb = c & (NSTAGE - 1);
        const uint32_t aS = aBase + sb * ASTG;
        const uint32_t bS = bBase + sb * BSTG;

        #pragma unroll
        for (int s = 0; s < 2; s++) {
            const int k0 = 16 * s;
            uint32_t a[4][4];
            #pragma unroll
            for (int mi = 0; mi < 4; mi++)
                ldmx4(a[mi], aS + ((wm * 64 + mi * 16 + (lane & 15)) * 40
                                   + k0 + (lane >> 4) * 8) * 2);
            uint32_t b[4][2];
            #pragma unroll
            for (int pr = 0; pr < 2; pr++) {
                uint32_t r[4];
                if (TRB) {
                    ldmx4(r, bS + ((wn * 32 + pr * 16 + (lane & 15)) * 40
                                   + k0 + (lane >> 4) * 8) * 2);
                    b[2*pr+0][0] = r[0]; b[2*pr+0][1] = r[2];
                    b[2*pr+1][0] = r[1]; b[2*pr+1][1] = r[3];
                } else {
                    ldmx4t(r, bS + ((k0 + (lane & 15)) * 136
                                    + wn * 32 + pr * 16 + (lane >> 4) * 8) * 2);
                    b[2*pr+0][0] = r[0]; b[2*pr+0][1] = r[1];
                    b[2*pr+1][0] = r[2]; b[2*pr+1][1] = r[3];
                }
            }
            #pragma unroll
            for (int mi = 0; mi < 4; mi++)
                #pragma unroll
                for (int ni = 0; ni < 4; ni++)
                    mma_f16(d[mi][ni], a[mi], b[ni][0], b[ni][1]);
        }
        __syncthreads();
    }

    // ---- epilogue ----
    #pragma unroll
    for (int mi = 0; mi < 4; mi++) {
        #pragma unroll
        for (int hf = 0; hf < 2; hf++) {
            const int r = rowBlk + wm * 64 + mi * 16 + g + hf * 8;

            float invL = 1.0f;
            if (MODE == 3) invL = 1.0f / gL[bz * NTOK + r];

            #pragma unroll
            for (int ni = 0; ni < 4; ni++) {
                const int c = colBlk + wn * 32 + ni * 8 + 2 * t;
                float v0 = d[mi][ni][2 * hf + 0];
                float v1 = d[mi][ni][2 * hf + 1];

                if (MODE == 3) {
                    const size_t idx = ((size_t)(bz * NTOK + r)) * CC + c;
                    float2 pe = *(const float2*)&gPE[idx];
                    float2 zz = *(const float2*)&gZ[idx];
                    *(__half2*)&gTh[idx] =
                        __floats2half2_rn((v0 * invL + pe.x) * zz.x,
                                          (v1 * invL + pe.y) * zz.y);
                } else if (MODE == 0) {
                    const int seg = c >> 8;
                    const int cc = c & 255;
                    const size_t idx = (size_t)r * CC + cc;
                    __half2 hv = __floats2half2_rn(v0, v1);
                    __half* dst = (seg == 0) ? gQh : (seg == 1) ? gKh : gVh;
                    *(__half2*)&dst[idx] = hv;
                } else if (MODE == 1) {
                    float2 bb = *(const float2*)&bias[c];
                    float a0 = v0 + bb.x, a1 = v1 + bb.y;
                    float2 v;
                    v.x = 0.5f * a0 * (1.0f + erff(a0 * 0.70710678118654752f));
                    v.y = 0.5f * a1 * (1.0f + erff(a1 * 0.70710678118654752f));
                    *(float2*)&gZ[(size_t)r * CC + c] = v;
                } else {
                    *(float2*)&Out[(size_t)r * CC + c] = make_float2(v0, v1);
                }
            }
        }
    }
}

// ======================================================================
// QK GEMM: BK=64, 3-stage. Tile 128x128. bz = blockIdx.z + bzOff.
// Epilogue: gPh = half(exp(acc*0.0625)); gL[row] += rowsum.
// ======================================================================
#define QSTG 18432        // 128 * 144
#define QK_NST 3
#define SMQK (QK_NST * 2 * QSTG)   // 110592

__global__ void __launch_bounds__(256, 2)
hgemm_qk(const __half* __restrict__ A, const __half* __restrict__ B, int bzOff)
{
    extern __shared__ __align__(16) char sm[];
    const uint32_t smb = (uint32_t)__cvta_generic_to_shared(sm);

    const int tid  = threadIdx.x;
    const int wid  = tid >> 5;
    const int lane = tid & 31;
    const int g    = lane >> 2;
    const int t    = lane & 3;
    const int wm   = wid >> 2;
    const int wn   = wid & 3;

    const int bz     = blockIdx.z + bzOff;
    const int rowBlk = blockIdx.y * 128;
    const int colBlk = blockIdx.x * 128;
    const __half* Ab = A + (size_t)bz * NTOK * CC;
    const __half* Bb = B + (size_t)bz * NTOK * CC;
    const int NC = CC >> 6;    // 4

    float d[4][4][4];
    #pragma unroll
    for (int mi = 0; mi < 4; mi++)
        #pragma unroll
        for (int ni = 0; ni < 4; ni++)
            #pragma unroll
            for (int j = 0; j < 4; j++) d[mi][ni][j] = 0.0f;

    auto loadStage = [&](int c) {
        const int kt = c << 6;
        const int sb = c % QK_NST;
        const uint32_t aS = smb + sb * (2 * QSTG);
        const uint32_t bS = aS + QSTG;
        #pragma unroll
        for (int j = 0; j < 4; j++) {
            const int task = tid + j * 256;
            const int row = task >> 3, ch = task & 7;
            cpa16(aS + row * 144 + ch * 16,
                  Ab + (size_t)(rowBlk + row) * CC + kt + ch * 8);
        }
        #pragma unroll
        for (int j = 0; j < 4; j++) {
            const int task = tid + j * 256;
            const int row = task >> 3, ch = task & 7;
            cpa16(bS + row * 144 + ch * 16,
                  Bb + (size_t)(colBlk + row) * CC + kt + ch * 8);
        }
        asm volatile("cp.async.commit_group;");
    };

    loadStage(0); loadStage(1);

    for (int c = 0; c < NC; ++c) {
        waitK(NC - 1 - c, QK_NST - 2);
        __syncthreads();
        if (c + QK_NST - 1 < NC) loadStage(c + QK_NST - 1);

        const int sb = c % QK_NST;
        const uint32_t aS = smb + sb * (2 * QSTG);
        const uint32_t bS = aS + QSTG;

        #pragma unroll
        for (int s = 0; s < 4; s++) {
            const int k0 = 16 * s;
            uint32_t a[4][4];
            #pragma unroll
            for (int mi = 0; mi < 4; mi++)
                ldmx4(a[mi], aS + ((wm * 64 + mi * 16 + (lane & 15)) * 72
                                   + k0 + (lane >> 4) * 8) * 2);
            uint32_t b[4][2];
            #pragma unroll
            for (int pr = 0; pr < 2; pr++) {
                uint32_t r[4];
                ldmx4(r, bS + ((wn * 32 + pr * 16 + (lane & 15)) * 72
                               + k0 + (lane >> 4) * 8) * 2);
                b[2*pr+0][0] = r[0]; b[2*pr+0][1] = r[2];
                b[2*pr+1][0] = r[1]; b[2*pr+1][1] = r[3];
            }
            #pragma unroll
            for (int mi = 0; mi < 4; mi++)
                #pragma unroll
                for (int ni = 0; ni < 4; ni++)
                    mma_f16(d[mi][ni], a[mi], b[ni][0], b[ni][1]);
        }
        __syncthreads();
    }

    // ---- epilogue: E = exp(scale * acc), rowsum atomics ----
    #pragma unroll
    for (int mi = 0; mi < 4; mi++) {
        #pragma unroll
        for (int hf = 0; hf < 2; hf++) {
            const int r = rowBlk + wm * 64 + mi * 16 + g + hf * 8;
            float rsum = 0.0f;
            #pragma unroll
            for (int ni = 0; ni < 4; ni++) {
                const int c = colBlk + wn * 32 + ni * 8 + 2 * t;
                float e0 = __expf(d[mi][ni][2 * hf + 0] * 0.0625f);
                float e1 = __expf(d[mi][ni][2 * hf + 1] * 0.0625f);
                __half2 hv = __floats2half2_rn(e0, e1);
                *(__half2*)&gPh[(size_t)bz * NTOK * NTOK + (size_t)r * NTOK + c] = hv;
                rsum += __low2float(hv) + __high2float(hv);
            }
            rsum += __shfl_xor_sync(0xffffffffu, rsum, 1);
            rsum += __shfl_xor_sync(0xffffffffu, rsum, 2);
            if (t == 0) atomicAdd(&gL[bz * NTOK + r], rsum);
        }
    }
}

// ---------------- fused convert (x + 3 weights -> fp16) + zero gL ----------------
#define N2_X   (BNTOK * CC / 2)
#define N2_QKV (CC * 3 * CC / 2)
#define N2_GW  (CC * CC / 2)
__global__ void __launch_bounds__(256)
convert_all(const float* __restrict__ x, const float* __restrict__ Wqkv,
            const float* __restrict__ Wgate, const float* __restrict__ Wproj)
{
    int i = blockIdx.x * 256 + threadIdx.x;
    if (i < BNTOK) gL[i] = 0.0f;

    const float* src; __half* dst; int off;
    if (i < N2_X)                        { src = x;     dst = gXh;     off = i; }
    else if ((i -= N2_X) < N2_QKV)       { src = Wqkv;  dst = gWqkvh;  off = i; }
    else if ((i -= N2_QKV) < N2_GW)      { src = Wgate; dst = gWgateh; off = i; }
    else if ((i -= N2_GW) < N2_GW)       { src = Wproj; dst = gWprojh; off = i; }
    else return;
    float2 v = *(const float2*)(src + 2 * off);
    *(__half2*)(dst + 2 * off) = __floats2half2_rn(v.x, v.y);
}

// ---------------- depthwise 3x3 conv PE (half2 reads, fp32 out) ----------------
__global__ void __launch_bounds__(256)
dwconv_pe(const float* __restrict__ w, const float* __restrict__ bias)
{
    const int idx = blockIdx.x * 256 + threadIdx.x;   // over BNTOK * 128
    const int c2 = idx & 127;
    const int n = (idx >> 7) & (NTOK - 1);
    const int b = idx >> 19;
    const int h = n >> 6;
    const int wd = n & 63;
    const int c = 2 * c2;

    const __half* q = gQh + (size_t)b * NTOK * CC;
    float a0 = bias[c], a1 = bias[c + 1];
    #pragma unroll
    for (int di = -1; di <= 1; di++) {
        const int hh = h + di;
        if (hh < 0 || hh > 63) continue;
        #pragma unroll
        for (int dj = -1; dj <= 1; dj++) {
            const int w2 = wd + dj;
            if (w2 < 0 || w2 > 63) continue;
            float2 qv = __half22float2(*(const __half2*)&q[(size_t)(hh * 64 + w2) * CC + c]);
            const int wj = (di + 1) * 3 + (dj + 1);
            a0 = fmaf(qv.x, w[c * 9 + wj], a0);
            a1 = fmaf(qv.y, w[(c + 1) * 9 + wj], a1);
        }
    }
    *(float2*)&gPE[2 * (size_t)idx] = make_float2(a0, a1);
}

// ---------------- launch ----------------
extern "C" void kernel_launch(void* const* d_in, const int* in_sizes, int n_in,
                              void* d_out, int out_size)
{
    const float* x     = (const float*)d_in[0];
    const float* Wqkv  = (const float*)d_in[1];
    const float* Wgate = (const float*)d_in[2];
    const float* bgate = (const float*)d_in[3];
    const float* Wproj = (const float*)d_in[4];
    const float* pew   = (const float*)d_in[5];
    const float* peb   = (const float*)d_in[6];
    float* out = (float*)d_out;

    __half *pXh, *pWqkvh, *pWgateh, *pWprojh, *pQh, *pKh, *pVh, *pPh, *pTh;
    cudaGetSymbolAddress((void**)&pXh, gXh);
    cudaGetSymbolAddress((void**)&pWqkvh, gWqkvh);
    cudaGetSymbolAddress((void**)&pWgateh, gWgateh);
    cudaGetSymbolAddress((void**)&pWprojh, gWprojh);
    cudaGetSymbolAddress((void**)&pQh, gQh);
    cudaGetSymbolAddress((void**)&pKh, gKh);
    cudaGetSymbolAddress((void**)&pVh, gVh);
    cudaGetSymbolAddress((void**)&pPh, gPh);
    cudaGetSymbolAddress((void**)&pTh, gTh);

    // one-time streams + events
    static cudaStream_t s2 = nullptr, s3 = nullptr;
    static cudaEvent_t evFork = nullptr, evJoin = nullptr, evQK01 = nullptr, evPV01 = nullptr;
    if (s2 == nullptr) {
        cudaStreamCreateWithFlags(&s2, cudaStreamNonBlocking);
        cudaStreamCreateWithFlags(&s3, cudaStreamNonBlocking);
        cudaEventCreateWithFlags(&evFork, cudaEventDisableTiming);
        cudaEventCreateWithFlags(&evJoin, cudaEventDisableTiming);
        cudaEventCreateWithFlags(&evQK01, cudaEventDisableTiming);
        cudaEventCreateWithFlags(&evPV01, cudaEventDisableTiming);
    }

    constexpr int SMT = NSTAGE * (ASTG + BSTG_T);   // 75776
    cudaFuncSetAttribute(hgemm<0,0>, cudaFuncAttributeMaxDynamicSharedMemorySize, SMT);
    cudaFuncSetAttribute(hgemm<1,0>, cudaFuncAttributeMaxDynamicSharedMemorySize, SMT);
    cudaFuncSetAttribute(hgemm<3,0>, cudaFuncAttributeMaxDynamicSharedMemorySize, SMT);
    cudaFuncSetAttribute(hgemm<4,0>, cudaFuncAttributeMaxDynamicSharedMemorySize, SMT);
    cudaFuncSetAttribute(hgemm_qk, cudaFuncAttributeMaxDynamicSharedMemorySize, SMQK);

    // 0) converts + zero row sums
    const int cvt_n = N2_X + N2_QKV + 2 * N2_GW;
    convert_all<<<dim3((cvt_n + 255) / 256), 256>>>(x, Wqkv, Wgate, Wproj);

    // 1) qkv = x @ W_qkv -> gQh/gKh/gVh
    hgemm<0,0><<<dim3(6,128,1), 256, SMT>>>(pXh, pWqkvh, nullptr, 256, 256, 768,
                                            0, 0, nullptr, 0);

    // fork: gate + dwconv on s2
    cudaEventRecord(evFork, 0);
    cudaStreamWaitEvent(s2, evFork, 0);
    hgemm<1,0><<<dim3(2,128,1), 256, SMT, s2>>>(pXh, pWgateh, nullptr, 256, 256, 256,
                                                0, 0, bgate, 0);
    dwconv_pe<<<dim3(BNTOK * 128 / 256), 256, 0, s2>>>(pew, peb);
    cudaEventRecord(evJoin, s2);

    // 2a) QK batches 0-1 on main
    hgemm_qk<<<dim3(32,32,2), 256, SMQK>>>(pQh, pKh, 0);
    cudaEventRecord(evQK01, 0);

    // 2b) QK batches 2-3 on main ‖ PV batches 0-1 on s3
    hgemm_qk<<<dim3(32,32,2), 256, SMQK>>>(pQh, pKh, 2);

    cudaStreamWaitEvent(s3, evQK01, 0);
    cudaStreamWaitEvent(s3, evJoin, 0);
    hgemm<3,0><<<dim3(2,32,2), 256, SMT, s3>>>(
        pPh, pVh, nullptr, 4096, 4096, 256,
        (size_t)NTOK * NTOK, (size_t)NTOK * CC, nullptr, 0);
    cudaEventRecord(evPV01, s3);

    // 3) PV batches 2-3 on main (after QK 2-3; needs gate/dwconv too)
    cudaStreamWaitEvent(0, evJoin, 0);
    hgemm<3,0><<<dim3(2,32,2), 256, SMT>>>(
        pPh + (size_t)2 * NTOK * NTOK, pVh + (size_t)2 * NTOK * CC, nullptr,
        4096, 4096, 256, (size_t)NTOK * NTOK, (size_t)NTOK * CC, nullptr, 2);

    // 4) join PV01, then proj
    cudaStreamWaitEvent(0, evPV01, 0);
    hgemm<4,0><<<dim3(2,128,1), 256, SMT>>>(pTh, pWprojh, out, 256, 256, 256,
                                            0, 0, nullptr, 0);
}

// round 17
// speedup vs baseline: 1.5766x; 1.0024x over previous
#include <cuda_runtime.h>
#include <cuda_fp16.h>
#include <math.h>
#include <stdint.h>

#define BB 4
#define NTOK 4096
#define CC 256
#define BNTOK (BB * NTOK)   // 16384

// ---------------- static scratch ----------------
__device__ __half gQh [(size_t)BNTOK * CC];
__device__ __half gKh [(size_t)BNTOK * CC];
__device__ __half gVh [(size_t)BNTOK * CC];
__device__ float  gZ  [(size_t)BNTOK * CC];
__device__ float  gPE [(size_t)BNTOK * CC];
__device__ __half gTh [(size_t)BNTOK * CC];
__device__ __half gPh [(size_t)BB * NTOK * NTOK];    // 128 MB: E = exp(scaled logits)
__device__ float  gL  [BNTOK];                       // row sums of E
__device__ __half gXh [(size_t)BNTOK * CC];
__device__ __half gWqkvh[CC * 3 * CC];
__device__ __half gWgateh[CC * CC];
__device__ __half gWprojh[CC * CC];

__device__ __forceinline__ void cpa16(uint32_t dst, const void* src) {
    asm volatile("cp.async.ca.shared.global [%0], [%1], 16;" :: "r"(dst), "l"(src));
}
__device__ __forceinline__ void cpa16cg(uint32_t dst, const void* src) {
    asm volatile("cp.async.cg.shared.global [%0], [%1], 16;" :: "r"(dst), "l"(src));
}
__device__ __forceinline__ void ldmx4(uint32_t r[4], uint32_t addr) {
    asm volatile("ldmatrix.sync.aligned.m8n8.x4.shared.b16 {%0,%1,%2,%3}, [%4];"
                 : "=r"(r[0]), "=r"(r[1]), "=r"(r[2]), "=r"(r[3]) : "r"(addr));
}
__device__ __forceinline__ void ldmx4t(uint32_t r[4], uint32_t addr) {
    asm volatile("ldmatrix.sync.aligned.m8n8.x4.trans.shared.b16 {%0,%1,%2,%3}, [%4];"
                 : "=r"(r[0]), "=r"(r[1]), "=r"(r[2]), "=r"(r[3]) : "r"(addr));
}
__device__ __forceinline__ void mma_f16(float d[4], const uint32_t a[4],
                                        uint32_t b0, uint32_t b1) {
    asm volatile(
        "mma.sync.aligned.m16n8k16.row.col.f32.f16.f16.f32 "
        "{%0,%1,%2,%3}, {%4,%5,%6,%7}, {%8,%9}, {%0,%1,%2,%3};"
        : "+f"(d[0]), "+f"(d[1]), "+f"(d[2]), "+f"(d[3])
        : "r"(a[0]), "r"(a[1]), "r"(a[2]), "r"(a[3]), "r"(b0), "r"(b1));
}
__device__ __forceinline__ void waitK(int n, int cap) {
    n = n < cap ? n : cap;
    switch (n) {
        case 0: asm volatile("cp.async.wait_group 0;"); break;
        case 1: asm volatile("cp.async.wait_group 1;"); break;
        default: asm volatile("cp.async.wait_group 2;"); break;
    }
}

#define ASTG 10240                 // A stage: 128 rows * 80 B
#define BSTG_D 10240               // B direct stage
#define BSTG_T 8704                // B trans stage: 32 rows * 272 B
#define NSTAGE 4

// ======================================================================
// fp16 GEMM: 256 thr, tile 128x128, BK=32, 4-stage.
// MODE 0: qkv split -> gQh/gKh/gVh
// MODE 1: gZ = gelu(acc+bias) (fp32)
// MODE 3: gTh = half((acc/L + gPE) * gZ)   bz = blockIdx.z + bzOff
// MODE 4: Out = acc (fp32)
// ======================================================================
template<int MODE, int TRB>
__global__ void __launch_bounds__(256, 2)
hgemm(const __half* __restrict__ A, const __half* __restrict__ B, float* __restrict__ Out,
      int K, int lda, int ldb, size_t sA, size_t sB, const float* __restrict__ bias,
      int bzOff)
{
    extern __shared__ __align__(16) char sm[];
    constexpr int BSTG = TRB ? BSTG_D : BSTG_T;
    const uint32_t smb = (uint32_t)__cvta_generic_to_shared(sm);
    const uint32_t aBase = smb;
    const uint32_t bBase = smb + NSTAGE * ASTG;

    const int tid  = threadIdx.x;
    const int wid  = tid >> 5;
    const int lane = tid & 31;
    const int g    = lane >> 2;
    const int t    = lane & 3;
    const int wm   = wid >> 2;
    const int wn   = wid & 3;

    const int bz     = blockIdx.z + bzOff;
    const int rowBlk = blockIdx.y * 128;
    const int colBlk = blockIdx.x * 128;
    const __half* Ab = A + (size_t)blockIdx.z * sA;
    const __half* Bb = B + (size_t)blockIdx.z * sB;
    const int NC = K >> 5;

    float d[4][4][4];
    #pragma unroll
    for (int mi = 0; mi < 4; mi++)
        #pragma unroll
        for (int ni = 0; ni < 4; ni++)
            #pragma unroll
            for (int j = 0; j < 4; j++) d[mi][ni][j] = 0.0f;

    auto loadStage = [&](int c) {
        const int kt = c << 5;
        const int sb = c & (NSTAGE - 1);
        const uint32_t aS = aBase + sb * ASTG;
        #pragma unroll
        for (int j = 0; j < 2; j++) {
            const int task = tid + j * 256;
            const int row = task >> 2, ch = task & 3;
            if (MODE == 3)
                cpa16cg(aS + row * 80 + ch * 16,
                        Ab + (size_t)(rowBlk + row) * lda + kt + ch * 8);
            else
                cpa16(aS + row * 80 + ch * 16,
                      Ab + (size_t)(rowBlk + row) * lda + kt + ch * 8);
        }
        const uint32_t bS = bBase + sb * BSTG;
        if (TRB) {
            #pragma unroll
            for (int j = 0; j < 2; j++) {
                const int task = tid + j * 256;
                const int row = task >> 2, ch = task & 3;
                cpa16(bS + row * 80 + ch * 16,
                      Bb + (size_t)(colBlk + row) * ldb + kt + ch * 8);
            }
        } else {
            #pragma unroll
            for (int j = 0; j < 2; j++) {
                const int task = tid + j * 256;
                const int row = task >> 4, ch = task & 15;
                cpa16(bS + row * 272 + ch * 16,
                      Bb + (size_t)(kt + row) * ldb + colBlk + ch * 8);
            }
        }
        asm volatile("cp.async.commit_group;");
    };

    loadStage(0); loadStage(1); loadStage(2);

    for (int c = 0; c < NC; ++c) {
        waitK(NC - 1 - c, NSTAGE - 2);
        __syncthreads();
        if (c + 3 < NC) loadStage(c + 3);

        const int sb = c & (NSTAGE - 1);
        const uint32_t aS = aBase + sb * ASTG;
        const uint32_t bS = bBase + sb * BSTG;

        #pragma unroll
        for (int s = 0; s < 2; s++) {
            const int k0 = 16 * s;
            uint32_t a[4][4];
            #pragma unroll
            for (int mi = 0; mi < 4; mi++)
                ldmx4(a[mi], aS + ((wm * 64 + mi * 16 + (lane & 15)) * 40
                                   + k0 + (lane >> 4) * 8) * 2);
            uint32_t b[4][2];
            #pragma unroll
            for (int pr = 0; pr < 2; pr++) {
                uint32_t r[4];
                if (TRB) {
                    ldmx4(r, bS + ((wn * 32 + pr * 16 + (lane & 15)) * 40
                                   + k0 + (lane >> 4) * 8) * 2);
                    b[2*pr+0][0] = r[0]; b[2*pr+0][1] = r[2];
                    b[2*pr+1][0] = r[1]; b[2*pr+1][1] = r[3];
                } else {
                    ldmx4t(r, bS + ((k0 + (lane & 15)) * 136
                                    + wn * 32 + pr * 16 + (lane >> 4) * 8) * 2);
                    b[2*pr+0][0] = r[0]; b[2*pr+0][1] = r[1];
                    b[2*pr+1][0] = r[2]; b[2*pr+1][1] = r[3];
                }
            }
            #pragma unroll
            for (int mi = 0; mi < 4; mi++)
                #pragma unroll
                for (int ni = 0; ni < 4; ni++)
                    mma_f16(d[mi][ni], a[mi], b[ni][0], b[ni][1]);
        }
        __syncthreads();
    }

    // ---- epilogue ----
    #pragma unroll
    for (int mi = 0; mi < 4; mi++) {
        #pragma unroll
        for (int hf = 0; hf < 2; hf++) {
            const int r = rowBlk + wm * 64 + mi * 16 + g + hf * 8;

            float invL = 1.0f;
            if (MODE == 3) invL = 1.0f / gL[bz * NTOK + r];

            #pragma unroll
            for (int ni = 0; ni < 4; ni++) {
                const int c = colBlk + wn * 32 + ni * 8 + 2 * t;
                float v0 = d[mi][ni][2 * hf + 0];
                float v1 = d[mi][ni][2 * hf + 1];

                if (MODE == 3) {
                    const size_t idx = ((size_t)(bz * NTOK + r)) * CC + c;
                    float2 pe = *(const float2*)&gPE[idx];
                    float2 zz = *(const float2*)&gZ[idx];
                    *(__half2*)&gTh[idx] =
                        __floats2half2_rn((v0 * invL + pe.x) * zz.x,
                                          (v1 * invL + pe.y) * zz.y);
                } else if (MODE == 0) {
                    const int seg = c >> 8;
                    const int cc = c & 255;
                    const size_t idx = (size_t)r * CC + cc;
                    __half2 hv = __floats2half2_rn(v0, v1);
                    __half* dst = (seg == 0) ? gQh : (seg == 1) ? gKh : gVh;
                    *(__half2*)&dst[idx] = hv;
                } else if (MODE == 1) {
                    float2 bb = *(const float2*)&bias[c];
                    float a0 = v0 + bb.x, a1 = v1 + bb.y;
                    float2 v;
                    v.x = 0.5f * a0 * (1.0f + erff(a0 * 0.70710678118654752f));
                    v.y = 0.5f * a1 * (1.0f + erff(a1 * 0.70710678118654752f));
                    *(float2*)&gZ[(size_t)r * CC + c] = v;
                } else {
                    *(float2*)&Out[(size_t)r * CC + c] = make_float2(v0, v1);
                }
            }
        }
    }
}

// ======================================================================
// QK GEMM: BK=64, 3-stage. Tile 128x128. bz = blockIdx.z + bzOff.
// Epilogue: gPh = half(exp(acc*0.0625)); gL[row] += rowsum.
// ======================================================================
#define QSTG 18432        // 128 * 144
#define QK_NST 3
#define SMQK (QK_NST * 2 * QSTG)   // 110592

__global__ void __launch_bounds__(256, 2)
hgemm_qk(const __half* __restrict__ A, const __half* __restrict__ B, int bzOff)
{
    extern __shared__ __align__(16) char sm[];
    const uint32_t smb = (uint32_t)__cvta_generic_to_shared(sm);

    const int tid  = threadIdx.x;
    const int wid  = tid >> 5;
    const int lane = tid & 31;
    const int g    = lane >> 2;
    const int t    = lane & 3;
    const int wm   = wid >> 2;
    const int wn   = wid & 3;

    const int bz     = blockIdx.z + bzOff;
    const int rowBlk = blockIdx.y * 128;
    const int colBlk = blockIdx.x * 128;
    const __half* Ab = A + (size_t)bz * NTOK * CC;
    const __half* Bb = B + (size_t)bz * NTOK * CC;
    const int NC = CC >> 6;    // 4

    float d[4][4][4];
    #pragma unroll
    for (int mi = 0; mi < 4; mi++)
        #pragma unroll
        for (int ni = 0; ni < 4; ni++)
            #pragma unroll
            for (int j = 0; j < 4; j++) d[mi][ni][j] = 0.0f;

    auto loadStage = [&](int c) {
        const int kt = c << 6;
        const int sb = c % QK_NST;
        const uint32_t aS = smb + sb * (2 * QSTG);
        const uint32_t bS = aS + QSTG;
        #pragma unroll
        for (int j = 0; j < 4; j++) {
            const int task = tid + j * 256;
            const int row = task >> 3, ch = task & 7;
            cpa16(aS + row * 144 + ch * 16,
                  Ab + (size_t)(rowBlk + row) * CC + kt + ch * 8);
        }
        #pragma unroll
        for (int j = 0; j < 4; j++) {
            const int task = tid + j * 256;
            const int row = task >> 3, ch = task & 7;
            cpa16(bS + row * 144 + ch * 16,
                  Bb + (size_t)(colBlk + row) * CC + kt + ch * 8);
        }
        asm volatile("cp.async.commit_group;");
    };

    loadStage(0); loadStage(1);

    for (int c = 0; c < NC; ++c) {
        waitK(NC - 1 - c, QK_NST - 2);
        __syncthreads();
        if (c + QK_NST - 1 < NC) loadStage(c + QK_NST - 1);

        const int sb = c % QK_NST;
        const uint32_t aS = smb + sb * (2 * QSTG);
        const uint32_t bS = aS + QSTG;

        #pragma unroll
        for (int s = 0; s < 4; s++) {
            const int k0 = 16 * s;
            uint32_t a[4][4];
            #pragma unroll
            for (int mi = 0; mi < 4; mi++)
                ldmx4(a[mi], aS + ((wm * 64 + mi * 16 + (lane & 15)) * 72
                                   + k0 + (lane >> 4) * 8) * 2);
            uint32_t b[4][2];
            #pragma unroll
            for (int pr = 0; pr < 2; pr++) {
                uint32_t r[4];
                ldmx4(r, bS + ((wn * 32 + pr * 16 + (lane & 15)) * 72
                               + k0 + (lane >> 4) * 8) * 2);
                b[2*pr+0][0] = r[0]; b[2*pr+0][1] = r[2];
                b[2*pr+1][0] = r[1]; b[2*pr+1][1] = r[3];
            }
            #pragma unroll
            for (int mi = 0; mi < 4; mi++)
                #pragma unroll
                for (int ni = 0; ni < 4; ni++)
                    mma_f16(d[mi][ni], a[mi], b[ni][0], b[ni][1]);
        }
        __syncthreads();
    }

    // ---- epilogue: E = exp(scale * acc), rowsum atomics ----
    #pragma unroll
    for (int mi = 0; mi < 4; mi++) {
        #pragma unroll
        for (int hf = 0; hf < 2; hf++) {
            const int r = rowBlk + wm * 64 + mi * 16 + g + hf * 8;
            float rsum = 0.0f;
            #pragma unroll
            for (int ni = 0; ni < 4; ni++) {
                const int c = colBlk + wn * 32 + ni * 8 + 2 * t;
                float e0 = __expf(d[mi][ni][2 * hf + 0] * 0.0625f);
                float e1 = __expf(d[mi][ni][2 * hf + 1] * 0.0625f);
                __half2 hv = __floats2half2_rn(e0, e1);
                *(__half2*)&gPh[(size_t)bz * NTOK * NTOK + (size_t)r * NTOK + c] = hv;
                rsum += __low2float(hv) + __high2float(hv);
            }
            rsum += __shfl_xor_sync(0xffffffffu, rsum, 1);
            rsum += __shfl_xor_sync(0xffffffffu, rsum, 2);
            if (t == 0) atomicAdd(&gL[bz * NTOK + r], rsum);
        }
    }
}

// ---------------- fused convert (x + 3 weights -> fp16) + zero gL ----------------
#define N2_X   (BNTOK * CC / 2)
#define N2_QKV (CC * 3 * CC / 2)
#define N2_GW  (CC * CC / 2)
__global__ void __launch_bounds__(256)
convert_all(const float* __restrict__ x, const float* __restrict__ Wqkv,
            const float* __restrict__ Wgate, const float* __restrict__ Wproj)
{
    int i = blockIdx.x * 256 + threadIdx.x;
    if (i < BNTOK) gL[i] = 0.0f;

    const float* src; __half* dst; int off;
    if (i < N2_X)                        { src = x;     dst = gXh;     off = i; }
    else if ((i -= N2_X) < N2_QKV)       { src = Wqkv;  dst = gWqkvh;  off = i; }
    else if ((i -= N2_QKV) < N2_GW)      { src = Wgate; dst = gWgateh; off = i; }
    else if ((i -= N2_GW) < N2_GW)       { src = Wproj; dst = gWprojh; off = i; }
    else return;
    float2 v = *(const float2*)(src + 2 * off);
    *(__half2*)(dst + 2 * off) = __floats2half2_rn(v.x, v.y);
}

// ---------------- depthwise 3x3 conv PE (half2 reads, fp32 out) ----------------
__global__ void __launch_bounds__(256)
dwconv_pe(const float* __restrict__ w, const float* __restrict__ bias)
{
    const int idx = blockIdx.x * 256 + threadIdx.x;   // over BNTOK * 128
    const int c2 = idx & 127;
    const int n = (idx >> 7) & (NTOK - 1);
    const int b = idx >> 19;
    const int h = n >> 6;
    const int wd = n & 63;
    const int c = 2 * c2;

    const __half* q = gQh + (size_t)b * NTOK * CC;
    float a0 = bias[c], a1 = bias[c + 1];
    #pragma unroll
    for (int di = -1; di <= 1; di++) {
        const int hh = h + di;
        if (hh < 0 || hh > 63) continue;
        #pragma unroll
        for (int dj = -1; dj <= 1; dj++) {
            const int w2 = wd + dj;
            if (w2 < 0 || w2 > 63) continue;
            float2 qv = __half22float2(*(const __half2*)&q[(size_t)(hh * 64 + w2) * CC + c]);
            const int wj = (di + 1) * 3 + (dj + 1);
            a0 = fmaf(qv.x, w[c * 9 + wj], a0);
            a1 = fmaf(qv.y, w[(c + 1) * 9 + wj], a1);
        }
    }
    *(float2*)&gPE[2 * (size_t)idx] = make_float2(a0, a1);
}

// ---------------- launch ----------------
extern "C" void kernel_launch(void* const* d_in, const int* in_sizes, int n_in,
                              void* d_out, int out_size)
{
    const float* x     = (const float*)d_in[0];
    const float* Wqkv  = (const float*)d_in[1];
    const float* Wgate = (const float*)d_in[2];
    const float* bgate = (const float*)d_in[3];
    const float* Wproj = (const float*)d_in[4];
    const float* pew   = (const float*)d_in[5];
    const float* peb   = (const float*)d_in[6];
    float* out = (float*)d_out;

    __half *pXh, *pWqkvh, *pWgateh, *pWprojh, *pQh, *pKh, *pVh, *pPh, *pTh;
    cudaGetSymbolAddress((void**)&pXh, gXh);
    cudaGetSymbolAddress((void**)&pWqkvh, gWqkvh);
    cudaGetSymbolAddress((void**)&pWgateh, gWgateh);
    cudaGetSymbolAddress((void**)&pWprojh, gWprojh);
    cudaGetSymbolAddress((void**)&pQh, gQh);
    cudaGetSymbolAddress((void**)&pKh, gKh);
    cudaGetSymbolAddress((void**)&pVh, gVh);
    cudaGetSymbolAddress((void**)&pPh, gPh);
    cudaGetSymbolAddress((void**)&pTh, gTh);

    // one-time streams + events
    static cudaStream_t s2 = nullptr, s3 = nullptr;
    static cudaEvent_t evFork = nullptr, evJoin = nullptr, evQK01 = nullptr;
    static cudaEvent_t evProj01 = nullptr;
    if (s2 == nullptr) {
        cudaStreamCreateWithFlags(&s2, cudaStreamNonBlocking);
        cudaStreamCreateWithFlags(&s3, cudaStreamNonBlocking);
        cudaEventCreateWithFlags(&evFork, cudaEventDisableTiming);
        cudaEventCreateWithFlags(&evJoin, cudaEventDisableTiming);
        cudaEventCreateWithFlags(&evQK01, cudaEventDisableTiming);
        cudaEventCreateWithFlags(&evProj01, cudaEventDisableTiming);
    }

    constexpr int SMT = NSTAGE * (ASTG + BSTG_T);   // 75776
    cudaFuncSetAttribute(hgemm<0,0>, cudaFuncAttributeMaxDynamicSharedMemorySize, SMT);
    cudaFuncSetAttribute(hgemm<1,0>, cudaFuncAttributeMaxDynamicSharedMemorySize, SMT);
    cudaFuncSetAttribute(hgemm<3,0>, cudaFuncAttributeMaxDynamicSharedMemorySize, SMT);
    cudaFuncSetAttribute(hgemm<4,0>, cudaFuncAttributeMaxDynamicSharedMemorySize, SMT);
    cudaFuncSetAttribute(hgemm_qk, cudaFuncAttributeMaxDynamicSharedMemorySize, SMQK);

    // 0) converts + zero row sums
    const int cvt_n = N2_X + N2_QKV + 2 * N2_GW;
    convert_all<<<dim3((cvt_n + 255) / 256), 256>>>(x, Wqkv, Wgate, Wproj);

    // 1) qkv = x @ W_qkv -> gQh/gKh/gVh
    hgemm<0,0><<<dim3(6,128,1), 256, SMT>>>(pXh, pWqkvh, nullptr, 256, 256, 768,
                                            0, 0, nullptr, 0);

    // fork: gate + dwconv on s2
    cudaEventRecord(evFork, 0);
    cudaStreamWaitEvent(s2, evFork, 0);
    hgemm<1,0><<<dim3(2,128,1), 256, SMT, s2>>>(pXh, pWgateh, nullptr, 256, 256, 256,
                                                0, 0, bgate, 0);
    dwconv_pe<<<dim3(BNTOK * 128 / 256), 256, 0, s2>>>(pew, peb);
    cudaEventRecord(evJoin, s2);

    // 2a) QK batches 0-1 on main
    hgemm_qk<<<dim3(32,32,2), 256, SMQK>>>(pQh, pKh, 0);
    cudaEventRecord(evQK01, 0);

    // 2b) QK batches 2-3 on main ‖ PV batches 0-1 then proj(0-1) on s3
    hgemm_qk<<<dim3(32,32,2), 256, SMQK>>>(pQh, pKh, 2);

    cudaStreamWaitEvent(s3, evQK01, 0);
    cudaStreamWaitEvent(s3, evJoin, 0);
    hgemm<3,0><<<dim3(2,32,2), 256, SMT, s3>>>(
        pPh, pVh, nullptr, 4096, 4096, 256,
        (size_t)NTOK * NTOK, (size_t)NTOK * CC, nullptr, 0);
    // proj for batches 0-1 (rows [0, 8192)) on s3 — overlaps PV(2-3) on main
    hgemm<4,0><<<dim3(2,64,1), 256, SMT, s3>>>(pTh, pWprojh, out, 256, 256, 256,
                                               0, 0, nullptr, 0);
    cudaEventRecord(evProj01, s3);

    // 3) PV batches 2-3 on main (after QK 2-3; needs gate/dwconv too)
    cudaStreamWaitEvent(0, evJoin, 0);
    hgemm<3,0><<<dim3(2,32,2), 256, SMT>>>(
        pPh + (size_t)2 * NTOK * NTOK, pVh + (size_t)2 * NTOK * CC, nullptr,
        4096, 4096, 256, (size_t)NTOK * NTOK, (size_t)NTOK * CC, nullptr, 2);

    // 4) proj for batches 2-3 (rows [8192, 16384)), then join proj01
    hgemm<4,0><<<dim3(2,64,1), 256, SMT>>>(pTh + (size_t)2 * NTOK * CC, pWprojh,
                                           out + (size_t)2 * NTOK * CC,
                                           256, 256, 256, 0, 0, nullptr, 0);
    cudaStreamWaitEvent(0, evProj01, 0);
}